// round 16
// baseline (speedup 1.0000x reference)
#include <cuda_runtime.h>
#include <cuda_bf16.h>
#include <cuda_fp16.h>
#include <cstdint>

typedef long long LL;

// ---------------- problem constants ----------------
#define BB   2
#define SS   1024
#define BS   2048          // B*S
#define DIM  4096
#define HH   32
#define QL   1536
#define KVL  512
#define NOPE 128
#define ROPE 64
#define VD   128
#define QKH  192           // NOPE+ROPE
#define CAT  576           // KVL+ROPE
#define QD   6144          // H*QKH
#define QKVW 2112          // QL + CAT
#define KVW  320           // K_head(128) | V(128) | k_pe(64)

#define NEGV   (-1e9f)
#define SCALEV 0.07216878364870322f   // 192^-0.5
#define EPSV   1e-6f

// ---------------- scratch (device globals) ----------
__device__ float g_wcat [(LL)DIM * QKVW];        // [wq_a ‖ wkv_a]
__device__ float g_qkv  [(LL)BS * QKVW];         // [qlora | kv] per row
__device__ float g_kvcat[(LL)BS * CAT];          // [norm(c_kv) | rope(k_pe)]
__device__ float g_q    [(LL)BS * QD];           // rope applied in place on pe part
__device__ float g_KV   [64LL * SS * KVW];       // (b,h,t,320) = [K_head|V|k_pe]
__device__ float g_scores[64LL * SS * SS];       // (b,h,s,t) — causal region only
__device__ float2 g_sstat[64LL * SS];            // per (bh,row): {rowmax, 1/sum}
__device__ float g_proj [(LL)BS * DIM];          // (bs, h*VD+d)

// ---------------- split-FP16 tensor-core tiled GEMM ----------------
// C[m,n] = sum_k A[m,k] * B(k,n) ; TB: B stored [N,K] row-major (A @ B^T)
// EPI==1: scores epilogue (v*SCALE + causal NEG); fully-masked tiles skipped.
// CK: causal K-bound (k limited to m0+128)
// NP: split passes. 3: ah*bh+ah*bl+al*bh  2: ah*bh+ah*bl  1: ah*bh
// SM: softmax-on-A (a = exp(a-mx[row])*inv[row], stats from Sstat)
// KR: B column remap for [K_head|V|k_pe] rows — col = k + (k>=128 ? 128 : 0)
// CTA tile 128x128, BK=16, 8 warps (2m x 4n), warp tile 64x32.
static const int BM = 128, BN = 128, BK = 16;
#define PK 12      // u32 pitch for [row][k2] tiles

__device__ __forceinline__ void split2(float x, float y, uint32_t& hi, uint32_t& lo) {
    __half hx = __float2half_rn(x), hy = __float2half_rn(y);
    float rx = x - __half2float(hx);
    float ry = y - __half2float(hy);
    __half2 h = __halves2half2(hx, hy);
    __half2 l = __floats2half2_rn(rx, ry);
    hi = *reinterpret_cast<uint32_t*>(&h);
    lo = *reinterpret_cast<uint32_t*>(&l);
}
__device__ __forceinline__ uint32_t hi2(float x, float y) {
    __half2 h = __floats2half2_rn(x, y);
    return *reinterpret_cast<uint32_t*>(&h);
}
__device__ __forceinline__ void mma16(float c[4], const uint32_t a[4], const uint32_t b[2]) {
    asm volatile(
        "mma.sync.aligned.m16n8k16.row.col.f32.f16.f16.f32 "
        "{%0,%1,%2,%3},{%4,%5,%6,%7},{%8,%9},{%0,%1,%2,%3};\n"
        : "+f"(c[0]), "+f"(c[1]), "+f"(c[2]), "+f"(c[3])
        : "r"(a[0]), "r"(a[1]), "r"(a[2]), "r"(a[3]), "r"(b[0]), "r"(b[1]));
}

template<bool TB, int EPI, bool CK, int NP, int SM, int KR>
__global__ __launch_bounds__(256, 2)
void gemm_k(const float* __restrict__ A, const float* __restrict__ Bp,
            float* __restrict__ C,
            int M, int N, int K,
            int lda, int ldb, int ldc,
            LL bA1, LL bA2, LL bB1, LL bB2, LL bC1, LL bC2, int nz2,
            const float2* __restrict__ Sstat)
{
    const int z  = blockIdx.z;
    const int z1 = z / nz2;
    const int z2 = z - z1 * nz2;
    A  += z1 * bA1 + z2 * bA2;
    Bp += z1 * bB1 + z2 * bB2;
    C  += z1 * bC1 + z2 * bC2;

    const int m0  = blockIdx.y * BM;
    const int n0  = blockIdx.x * BN;
    const int tid = threadIdx.x;

    if (EPI == 1 && n0 >= m0 + BM) return;   // fully masked: never read — skip

    __shared__ uint32_t Ah[BM * PK];
    __shared__ uint32_t Al[(NP == 3) ? BM * PK : 1];
    __shared__ uint32_t Bh[BN * PK];
    __shared__ uint32_t Bl[(NP >= 2) ? BN * PK : 1];

    const int lane = tid & 31, warp = tid >> 5;
    const int wm = warp >> 2, wn = warp & 3;
    const int gp = lane >> 2, tg = lane & 3;

    float acc[4][4][4];
#pragma unroll
    for (int i = 0; i < 4; i++)
#pragma unroll
        for (int j = 0; j < 4; j++)
#pragma unroll
            for (int r = 0; r < 4; r++) acc[i][j][r] = 0.f;

    int Keff = K;
    if (CK) { int km = m0 + BM; Keff = (km < K) ? km : K; }

    const int am = tid >> 2;          // 0..63 rows (A / TB-B loads)
    const int ak = (tid & 3) << 2;    // k offset 0,4,8,12
    const int k2a = (tid & 3) << 1;   // k2 offset 0,2,4,6
    const int bnn  = tid & 127;
    const int bkh  = (tid >> 7) << 2;

    // hoisted per-row softmax stats for the two A rows this thread fills
    float smx0 = 0.f, sinv0 = 1.f, smx1 = 0.f, sinv1 = 1.f;
    if (SM) {
        float2 s0 = Sstat[(LL)z * SS + m0 + am];
        float2 s1 = Sstat[(LL)z * SS + m0 + am + 64];
        smx0 = s0.x; sinv0 = s0.y;
        smx1 = s1.x; sinv1 = s1.y;
    }

    for (int k0 = 0; k0 < Keff; k0 += BK) {
        // ---- A tile -> [m][k2] (hi, + lo if NP==3)
#pragma unroll
        for (int p = 0; p < 2; p++) {
            int m = am + (p << 6);
            float4 v = *reinterpret_cast<const float4*>(
                A + (LL)(m0 + m) * lda + k0 + ak);
            if (SM) {
                float mxv = p ? smx1 : smx0;
                float ivv = p ? sinv1 : sinv0;
                v.x = __expf(v.x - mxv) * ivv;
                v.y = __expf(v.y - mxv) * ivv;
                v.z = __expf(v.z - mxv) * ivv;
                v.w = __expf(v.w - mxv) * ivv;
            }
            if (NP == 3) {
                uint32_t h0, l0, h1, l1;
                split2(v.x, v.y, h0, l0);
                split2(v.z, v.w, h1, l1);
                Ah[m * PK + k2a]     = h0;  Ah[m * PK + k2a + 1] = h1;
                Al[m * PK + k2a]     = l0;  Al[m * PK + k2a + 1] = l1;
            } else {
                Ah[m * PK + k2a]     = hi2(v.x, v.y);
                Ah[m * PK + k2a + 1] = hi2(v.z, v.w);
            }
        }
        // ---- B tile -> [n][k2] (hi, + lo if NP>=2)
        if (!TB) {   // gmem [k][n]: transpose in flight
#pragma unroll
            for (int q = 0; q < 4; q++) {
                int kk = bkh + q;
                float f0 = 0.f, f1 = 0.f;
                if (n0 + bnn < N) {
                    f0 = Bp[(LL)(k0 + 2 * kk)     * ldb + n0 + bnn];
                    f1 = Bp[(LL)(k0 + 2 * kk + 1) * ldb + n0 + bnn];
                }
                if (NP >= 2) {
                    uint32_t h, l;
                    split2(f0, f1, h, l);
                    Bh[bnn * PK + kk] = h;
                    Bl[bnn * PK + kk] = l;
                } else {
                    Bh[bnn * PK + kk] = hi2(f0, f1);
                }
            }
        } else {     // gmem [n][k]
            int kcol = k0 + ak;
            if (KR) kcol += (kcol >= 128) ? 128 : 0;   // skip V block in KV rows
#pragma unroll
            for (int p = 0; p < 2; p++) {
                int n = am + (p << 6);
                float4 v = make_float4(0.f, 0.f, 0.f, 0.f);
                if (n0 + n < N)
                    v = *reinterpret_cast<const float4*>(
                        Bp + (LL)(n0 + n) * ldb + kcol);
                if (NP >= 2) {
                    uint32_t h0, l0, h1, l1;
                    split2(v.x, v.y, h0, l0);
                    split2(v.z, v.w, h1, l1);
                    Bh[n * PK + k2a]     = h0;  Bh[n * PK + k2a + 1] = h1;
                    Bl[n * PK + k2a]     = l0;  Bl[n * PK + k2a + 1] = l1;
                } else {
                    Bh[n * PK + k2a]     = hi2(v.x, v.y);
                    Bh[n * PK + k2a + 1] = hi2(v.z, v.w);
                }
            }
        }
        __syncthreads();

        uint32_t bhf[4][2], blf[4][2];
#pragma unroll
        for (int nf = 0; nf < 4; nf++) {
            int nb = (wn << 5) + (nf << 3) + gp;
            bhf[nf][0] = Bh[nb * PK + tg];
            bhf[nf][1] = Bh[nb * PK + tg + 4];
            if (NP >= 2) {
                blf[nf][0] = Bl[nb * PK + tg];
                blf[nf][1] = Bl[nb * PK + tg + 4];
            }
        }
#pragma unroll
        for (int mf = 0; mf < 4; mf++) {
            int mb = (wm << 6) + (mf << 4) + gp;
            int j0 = mb * PK + tg;
            int j1 = (mb + 8) * PK + tg;
            uint32_t ahf[4] = { Ah[j0], Ah[j1], Ah[j0 + 4], Ah[j1 + 4] };
#pragma unroll
            for (int nf = 0; nf < 4; nf++) {
                mma16(acc[mf][nf], ahf, bhf[nf]);
                if (NP >= 2) mma16(acc[mf][nf], ahf, blf[nf]);
            }
            if (NP == 3) {
                uint32_t alf[4] = { Al[j0], Al[j1], Al[j0 + 4], Al[j1 + 4] };
#pragma unroll
                for (int nf = 0; nf < 4; nf++)
                    mma16(acc[mf][nf], alf, bhf[nf]);
            }
        }
        __syncthreads();
    }

    // ---- store
#pragma unroll
    for (int mf = 0; mf < 4; mf++) {
#pragma unroll
        for (int nf = 0; nf < 4; nf++) {
            int n = n0 + (wn << 5) + (nf << 3) + 2 * tg;
#pragma unroll
            for (int h = 0; h < 2; h++) {
                int m = m0 + (wm << 6) + (mf << 4) + gp + h * 8;
                float2 v = make_float2(acc[mf][nf][2 * h], acc[mf][nf][2 * h + 1]);
                if (EPI == 1) {
                    v.x = v.x * SCALEV + ((n + 0 > m) ? NEGV : 0.f);
                    v.y = v.y * SCALEV + ((n + 1 > m) ? NEGV : 0.f);
                }
                LL ro = (LL)m * ldc;
                if (n + 1 < N) {
                    *reinterpret_cast<float2*>(C + ro + n) = v;
                } else {
                    if (n < N) C[ro + n] = v.x;
                    if (n + 1 < N) C[ro + n + 1] = v.y;
                }
            }
        }
    }
}

// ---- weight concat: wcat[k][0:1536]=wq_a[k], wcat[k][1536:2112]=wkv_a[k] ----
__global__ void wconcat_k(const float* __restrict__ wq_a,
                          const float* __restrict__ wkv_a,
                          float* __restrict__ wcat)
{
    int idx = blockIdx.x * 256 + threadIdx.x;          // float4 index
    int row = idx / (QKVW / 4);
    int c4  = idx - row * (QKVW / 4);
    if (row >= DIM) return;
    int c = c4 * 4;
    float4 v;
    if (c < QL) v = *reinterpret_cast<const float4*>(wq_a + (LL)row * QL + c);
    else        v = *reinterpret_cast<const float4*>(wkv_a + (LL)row * CAT + (c - QL));
    *reinterpret_cast<float4*>(wcat + (LL)row * QKVW + c) = v;
}

// ---------------- rmsnorm (in place, strided rows) ----------------
__global__ void rmsnorm_k(float* __restrict__ x, const float* __restrict__ w,
                          int len, int stride)
{
    float* row = x + (LL)blockIdx.x * stride;
    const int tid = threadIdx.x;
    float ss = 0.f;
    for (int i = tid; i < len; i += 256) { float v = row[i]; ss += v * v; }
    __shared__ float red[8];
    __shared__ float sc_s;
#pragma unroll
    for (int o = 16; o; o >>= 1) ss += __shfl_xor_sync(0xffffffffu, ss, o);
    if ((tid & 31) == 0) red[tid >> 5] = ss;
    __syncthreads();
    if (tid == 0) {
        float t = 0.f;
#pragma unroll
        for (int i = 0; i < 8; i++) t += red[i];
        sc_s = rsqrtf(t / (float)len + EPSV);
    }
    __syncthreads();
    float sc = sc_s;
    for (int i = tid; i < len; i += 256) row[i] = row[i] * sc * w[i];
}

// ---- kvpost: rmsnorm(c_kv)*w -> kvcat[0:512]; rope(k_pe) -> kvcat[512:576]
//      AND broadcast roped k_pe into KV[b][h][t][256:320] for all 32 heads.
__global__ void kvpost_k(const float* __restrict__ kv, const float* __restrict__ w,
                         const float* __restrict__ fc, float* __restrict__ o,
                         float* __restrict__ KV, int stride)
{
    const int bs = blockIdx.x;
    const float* row = kv + (LL)bs * stride;
    float* out = o + (LL)bs * CAT;
    const int tid = threadIdx.x;
    float2 v = *reinterpret_cast<const float2*>(row + 2 * tid);
    float ss = v.x * v.x + v.y * v.y;
    __shared__ float red[8];
    __shared__ float sc_s;
#pragma unroll
    for (int oo = 16; oo; oo >>= 1) ss += __shfl_xor_sync(0xffffffffu, ss, oo);
    if ((tid & 31) == 0) red[tid >> 5] = ss;
    __syncthreads();
    if (tid == 0) {
        float t = 0.f;
#pragma unroll
        for (int i = 0; i < 8; i++) t += red[i];
        sc_s = rsqrtf(t / (float)KVL + EPSV);
    }
    __syncthreads();
    float sc = sc_s;
    *reinterpret_cast<float2*>(out + 2 * tid) =
        make_float2(v.x * sc * w[2 * tid], v.y * sc * w[2 * tid + 1]);
    if (tid < 32) {
        int t = bs & (SS - 1);
        int b = bs >> 10;
        float e  = row[KVL + 2 * tid];
        float od = row[KVL + 2 * tid + 1];
        float c  = fc[t * ROPE + 2 * tid];
        float sn = fc[t * ROPE + 2 * tid + 1];
        float re = e * c - od * sn;
        float ro = e * sn + od * c;
        out[KVL + 2 * tid]     = re;
        out[KVL + 2 * tid + 1] = ro;
        float2 pr = make_float2(re, ro);
#pragma unroll
        for (int h = 0; h < HH; h++) {
            LL base = (((LL)(b * HH + h)) * SS + t) * KVW + 256 + 2 * tid;
            *reinterpret_cast<float2*>(KV + base) = pr;
        }
    }
}

// ---- rope(q_pe) IN PLACE on q[..., h*192+128 : h*192+192] ----
__global__ void ropeq_k(float* __restrict__ q, const float* __restrict__ fc)
{
    const int bs = blockIdx.x;
    const int s = bs & (SS - 1);
    for (int t = threadIdx.x; t < HH * 32; t += 256) {
        int h = t >> 5, i = t & 31;
        float* p = q + (LL)bs * QD + h * QKH + NOPE + 2 * i;
        float e = p[0], o = p[1];
        float c  = fc[s * ROPE + 2 * i];
        float sn = fc[s * ROPE + 2 * i + 1];
        p[0] = e * c - o * sn;
        p[1] = e * sn + o * c;
    }
}

// ---- softmax stats (single gmem pass, register-cached) ----
__global__ void smstat_k(const float* __restrict__ S, float2* __restrict__ stat)
{
    const LL row = blockIdx.x;               // bh*1024 + m
    const int m = (int)(row & (SS - 1));
    const float* r = S + row * SS;
    const int tid = threadIdx.x;             // 128 threads
    float v[8];
    int cnt = 0;
    float mx = -3.4e38f;
    for (int i = tid; i <= m; i += 128) {
        float x = r[i];
        v[cnt++] = x;
        mx = fmaxf(mx, x);
    }
    __shared__ float red[4];
    __shared__ float bval;
#pragma unroll
    for (int o = 16; o; o >>= 1) mx = fmaxf(mx, __shfl_xor_sync(0xffffffffu, mx, o));
    if ((tid & 31) == 0) red[tid >> 5] = mx;
    __syncthreads();
    if (tid == 0) {
        float t = fmaxf(fmaxf(red[0], red[1]), fmaxf(red[2], red[3]));
        bval = t;
    }
    __syncthreads();
    mx = bval;
    float sum = 0.f;
    for (int j = 0; j < cnt; j++) sum += __expf(v[j] - mx);
#pragma unroll
    for (int o = 16; o; o >>= 1) sum += __shfl_xor_sync(0xffffffffu, sum, o);
    if ((tid & 31) == 0) red[tid >> 5] = sum;
    __syncthreads();
    if (tid == 0) {
        float t = red[0] + red[1] + red[2] + red[3];
        stat[row] = make_float2(mx, 1.f / t);
    }
}

// ---------------- host ----------------
extern "C" void kernel_launch(void* const* d_in, const int* in_sizes, int n_in,
                              void* d_out, int out_size)
{
    (void)in_sizes; (void)n_in; (void)out_size;
    const float* x      = (const float*)d_in[0];
    const float* fc     = (const float*)d_in[1];
    /* mask d_in[2] handled analytically (start_pos == 0, causal) */
    const float* wq_a   = (const float*)d_in[3];
    const float* qnw    = (const float*)d_in[4];
    const float* wq_b   = (const float*)d_in[5];
    const float* wkv_a  = (const float*)d_in[6];
    const float* kvnw   = (const float*)d_in[7];
    const float* wkv_b  = (const float*)d_in[8];
    const float* wo     = (const float*)d_in[9];
    float* out = (float*)d_out;

    float *wcat, *qkv, *kvcat, *q, *KV, *scores, *proj;
    float2* sstat;
    cudaGetSymbolAddress((void**)&wcat,   g_wcat);
    cudaGetSymbolAddress((void**)&qkv,    g_qkv);
    cudaGetSymbolAddress((void**)&kvcat,  g_kvcat);
    cudaGetSymbolAddress((void**)&q,      g_q);
    cudaGetSymbolAddress((void**)&KV,     g_KV);
    cudaGetSymbolAddress((void**)&scores, g_scores);
    cudaGetSymbolAddress((void**)&sstat,  g_sstat);
    cudaGetSymbolAddress((void**)&proj,   g_proj);

    // one-time stream/event setup (correctness call precedes graph capture;
    // creation happens outside capture, capture encodes the fork/join)
    static cudaStream_t s2 = nullptr;
    static cudaEvent_t evA = nullptr, evB = nullptr;
    if (s2 == nullptr) {
        cudaStreamCreateWithFlags(&s2, cudaStreamNonBlocking);
        cudaEventCreateWithFlags(&evA, cudaEventDisableTiming);
        cudaEventCreateWithFlags(&evB, cudaEventDisableTiming);
    }

    // 0. wcat = [wq_a ‖ wkv_a]
    wconcat_k<<<(DIM * (QKVW / 4) + 255) / 256, 256>>>(wq_a, wkv_a, wcat);
    // 1+2 fused. qkv = x @ wcat          [2048,2112]   (1-pass) 272 CTAs
    gemm_k<false, 0, false, 1, 0, 0><<<dim3(17, 16, 1), 256>>>(
        x, wcat, qkv, BS, QKVW, DIM, DIM, QKVW, QKVW, 0, 0, 0, 0, 0, 0, 1, nullptr);
    // 3. rmsnorm(qlora) in place (rows inside qkv, stride 2112)
    rmsnorm_k<<<BS, 256>>>(qkv, qnw, QL, QKVW);
    // 4. kvpost -> kvcat; k_pe broadcast into KV[...,256:320]
    kvpost_k<<<BS, 256>>>(qkv + QL, kvnw, fc, kvcat, KV, QKVW);

    // ---- fork: kv branch on s2, q branch on default stream
    cudaEventRecord(evA, 0);
    cudaStreamWaitEvent(s2, evA, 0);
    // 5 (s2). KV[b][h][t][0:256] = kv_n @ wkv_b[h]^T  (K_head + V) (1-pass)
    gemm_k<true, 0, false, 1, 0, 0><<<dim3(2, 8, 64), 256, 0, s2>>>(
        kvcat, wkv_b, KV, SS, NOPE + VD, KVL,
        CAT, KVL, KVW,
        (LL)SS * CAT, 0,
        0, (LL)(NOPE + VD) * KVL,
        (LL)HH * SS * KVW, (LL)SS * KVW, HH, nullptr);
    cudaEventRecord(evB, s2);
    // 6 (default). q = qlora @ wq_b      [2048,6144]   (1-pass)
    gemm_k<false, 0, false, 1, 0, 0><<<dim3(48, 16, 1), 256>>>(
        qkv, wq_b, q, BS, QD, QL, QKVW, QD, QD, 0, 0, 0, 0, 0, 0, 1, nullptr);
    // 7 (default). rope(q_pe) in place on q
    ropeq_k<<<BS, 256>>>(q, fc);
    // ---- join
    cudaStreamWaitEvent(0, evB, 0);

    // 8. scores = q_head @ [K_head|k_pe]^T (*SCALE + causal; KREMAP)  (1-pass)
    gemm_k<true, 1, false, 1, 0, 1><<<dim3(8, 8, 64), 256>>>(
        q, KV, scores, SS, SS, QKH,
        QD, KVW, SS,
        (LL)SS * QD, QKH,
        (LL)HH * SS * KVW, (LL)SS * KVW,
        (LL)HH * SS * SS, (LL)SS * SS, HH, nullptr);
    // 9. per-row softmax stats over causal prefix (single pass)
    smstat_k<<<64 * SS, 128>>>(scores, sstat);
    // 10. PV: proj = softmax(scores) @ V (fused, causal K)  (1-pass, non-TB)
    gemm_k<false, 0, true, 1, 1, 0><<<dim3(1, 8, 64), 256>>>(
        scores, KV + 128, proj, SS, VD, SS,
        SS, KVW, DIM,
        (LL)HH * SS * SS, (LL)SS * SS,
        (LL)HH * SS * KVW, (LL)SS * KVW,
        (LL)SS * DIM, VD, HH, sstat);
    // 11. out = proj @ wo                [2048,4096]   (1-pass)
    gemm_k<false, 0, false, 1, 0, 0><<<dim3(32, 16, 1), 256>>>(
        proj, wo, out, BS, DIM, DIM, DIM, DIM, DIM, 0, 0, 0, 0, 0, 0, 1, nullptr);
}

// round 17
// speedup vs baseline: 1.2263x; 1.2263x over previous
#include <cuda_runtime.h>
#include <cuda_bf16.h>
#include <cuda_fp16.h>
#include <cstdint>

typedef long long LL;

// ---------------- problem constants ----------------
#define BB   2
#define SS   1024
#define BS   2048          // B*S
#define DIM  4096
#define HH   32
#define QL   1536
#define KVL  512
#define NOPE 128
#define ROPE 64
#define VD   128
#define QKH  192           // NOPE+ROPE
#define CAT  576           // KVL+ROPE
#define QD   6144          // H*QKH
#define QKVW 2112          // QL + CAT
#define KVW  320           // K_head(128) | V(128) | k_pe(64)

#define NEGV   (-1e9f)
#define SCALEV 0.07216878364870322f   // 192^-0.5
#define EPSV   1e-6f

// ---------------- scratch (device globals) ----------
__device__ float g_wcat [(LL)DIM * QKVW];        // [wq_a ‖ wkv_a]
__device__ float g_qkv  [(LL)BS * QKVW];         // [qlora | kv] per row
__device__ float g_kvcat[(LL)BS * CAT];          // [norm(c_kv) | rope(k_pe)]
__device__ float g_q    [(LL)BS * QD];           // rope applied in place on pe part
__device__ float g_KV   [64LL * SS * KVW];       // (b,h,t,320) = [K_head|V|k_pe]
__device__ float g_scores[64LL * SS * SS];       // (b,h,s,t) — causal region only
__device__ float2 g_sstat[64LL * SS];            // per (bh,row): {rowmax, 1/sum}
__device__ float g_proj [(LL)BS * DIM];          // (bs, h*VD+d)

// ---------------- split-FP16 tensor-core tiled GEMM (register-pipelined) ----
// C[m,n] = sum_k A[m,k] * B(k,n) ; TB: B stored [N,K] row-major (A @ B^T)
// EPI==1: scores epilogue (v*SCALE + causal NEG); fully-masked tiles skipped.
// CK: causal K-bound (k limited to m0+128)
// NP: 1 = pure fp16 single pass (hi only). (2/3-pass paths removed; all
//     launches run NP=1 per rounds 13-15 error budget.)
// SM: softmax-on-A (a = exp(a-mx[row])*inv[row], stats from Sstat)
// KR: B column remap for [K_head|V|k_pe] rows — col = k + (k>=128 ? 128 : 0)
// Pipeline: regs prefetch chunk k+1 gmem while MMA of chunk k runs from smem.
// CTA tile 128x128, BK=16, 8 warps (2m x 4n), warp tile 64x32.
static const int BM = 128, BN = 128, BK = 16;
#define PK 12      // u32 pitch for [row][k2] tiles

__device__ __forceinline__ uint32_t hi2(float x, float y) {
    __half2 h = __floats2half2_rn(x, y);
    return *reinterpret_cast<uint32_t*>(&h);
}
__device__ __forceinline__ void mma16(float c[4], const uint32_t a[4], const uint32_t b[2]) {
    asm volatile(
        "mma.sync.aligned.m16n8k16.row.col.f32.f16.f16.f32 "
        "{%0,%1,%2,%3},{%4,%5,%6,%7},{%8,%9},{%0,%1,%2,%3};\n"
        : "+f"(c[0]), "+f"(c[1]), "+f"(c[2]), "+f"(c[3])
        : "r"(a[0]), "r"(a[1]), "r"(a[2]), "r"(a[3]), "r"(b[0]), "r"(b[1]));
}

template<bool TB, int EPI, bool CK, int SM, int KR>
__global__ __launch_bounds__(256, 2)
void gemm_k(const float* __restrict__ A, const float* __restrict__ Bp,
            float* __restrict__ C,
            int M, int N, int K,
            int lda, int ldb, int ldc,
            LL bA1, LL bA2, LL bB1, LL bB2, LL bC1, LL bC2, int nz2,
            const float2* __restrict__ Sstat)
{
    const int z  = blockIdx.z;
    const int z1 = z / nz2;
    const int z2 = z - z1 * nz2;
    A  += z1 * bA1 + z2 * bA2;
    Bp += z1 * bB1 + z2 * bB2;
    C  += z1 * bC1 + z2 * bC2;

    const int m0  = blockIdx.y * BM;
    const int n0  = blockIdx.x * BN;
    const int tid = threadIdx.x;

    if (EPI == 1 && n0 >= m0 + BM) return;   // fully masked: never read — skip

    __shared__ uint32_t Ah[BM * PK];
    __shared__ uint32_t Bh[BN * PK];

    const int lane = tid & 31, warp = tid >> 5;
    const int wm = warp >> 2, wn = warp & 3;
    const int gp = lane >> 2, tg = lane & 3;

    float acc[4][4][4];
#pragma unroll
    for (int i = 0; i < 4; i++)
#pragma unroll
        for (int j = 0; j < 4; j++)
#pragma unroll
            for (int r = 0; r < 4; r++) acc[i][j][r] = 0.f;

    int Keff = K;
    if (CK) { int km = m0 + BM; Keff = (km < K) ? km : K; }

    const int am = tid >> 2;          // 0..63 rows (A / TB-B loads)
    const int ak = (tid & 3) << 2;    // k offset 0,4,8,12
    const int k2a = (tid & 3) << 1;   // k2 offset 0,2,4,6
    const int bnn  = tid & 127;
    const int bkh  = (tid >> 7) << 2;

    // hoisted per-row softmax stats for the two A rows this thread fills
    float smx0 = 0.f, sinv0 = 1.f, smx1 = 0.f, sinv1 = 1.f;
    if (SM) {
        float2 s0 = Sstat[(LL)z * SS + m0 + am];
        float2 s1 = Sstat[(LL)z * SS + m0 + am + 64];
        smx0 = s0.x; sinv0 = s0.y;
        smx1 = s1.x; sinv1 = s1.y;
    }

    // ---- prefetch registers
    float4 pa0, pa1;              // A rows am, am+64
    float4 pb0, pb1;              // B (TB) rows am, am+64
    float  pbn[8];                // B (non-TB) 4 k-pairs at column bnn

#define LOADCH(k0)                                                              \
    {                                                                           \
        pa0 = *reinterpret_cast<const float4*>(                                 \
            A + (LL)(m0 + am) * lda + (k0) + ak);                               \
        pa1 = *reinterpret_cast<const float4*>(                                 \
            A + (LL)(m0 + am + 64) * lda + (k0) + ak);                          \
        if (!TB) {                                                              \
            _Pragma("unroll")                                                   \
            for (int q = 0; q < 4; q++) {                                       \
                int kk = bkh + q;                                               \
                float f0 = 0.f, f1 = 0.f;                                       \
                if (n0 + bnn < N) {                                             \
                    f0 = Bp[(LL)((k0) + 2 * kk)     * ldb + n0 + bnn];          \
                    f1 = Bp[(LL)((k0) + 2 * kk + 1) * ldb + n0 + bnn];          \
                }                                                               \
                pbn[2 * q] = f0; pbn[2 * q + 1] = f1;                           \
            }                                                                   \
        } else {                                                                \
            int kcol = (k0) + ak;                                               \
            if (KR) kcol += (kcol >= 128) ? 128 : 0;                            \
            pb0 = make_float4(0.f, 0.f, 0.f, 0.f);                              \
            pb1 = make_float4(0.f, 0.f, 0.f, 0.f);                              \
            if (n0 + am < N)                                                    \
                pb0 = *reinterpret_cast<const float4*>(                         \
                    Bp + (LL)(n0 + am) * ldb + kcol);                           \
            if (n0 + am + 64 < N)                                               \
                pb1 = *reinterpret_cast<const float4*>(                         \
                    Bp + (LL)(n0 + am + 64) * ldb + kcol);                      \
        }                                                                       \
    }

#define STORECH()                                                               \
    {                                                                           \
        float4 va = pa0, vb = pa1;                                              \
        if (SM) {                                                               \
            va.x = __expf(va.x - smx0) * sinv0;                                 \
            va.y = __expf(va.y - smx0) * sinv0;                                 \
            va.z = __expf(va.z - smx0) * sinv0;                                 \
            va.w = __expf(va.w - smx0) * sinv0;                                 \
            vb.x = __expf(vb.x - smx1) * sinv1;                                 \
            vb.y = __expf(vb.y - smx1) * sinv1;                                 \
            vb.z = __expf(vb.z - smx1) * sinv1;                                 \
            vb.w = __expf(vb.w - smx1) * sinv1;                                 \
        }                                                                       \
        Ah[am * PK + k2a]            = hi2(va.x, va.y);                         \
        Ah[am * PK + k2a + 1]        = hi2(va.z, va.w);                         \
        Ah[(am + 64) * PK + k2a]     = hi2(vb.x, vb.y);                         \
        Ah[(am + 64) * PK + k2a + 1] = hi2(vb.z, vb.w);                         \
        if (!TB) {                                                              \
            _Pragma("unroll")                                                   \
            for (int q = 0; q < 4; q++)                                         \
                Bh[bnn * PK + bkh + q] = hi2(pbn[2 * q], pbn[2 * q + 1]);       \
        } else {                                                                \
            Bh[am * PK + k2a]            = hi2(pb0.x, pb0.y);                   \
            Bh[am * PK + k2a + 1]        = hi2(pb0.z, pb0.w);                   \
            Bh[(am + 64) * PK + k2a]     = hi2(pb1.x, pb1.y);                   \
            Bh[(am + 64) * PK + k2a + 1] = hi2(pb1.z, pb1.w);                   \
        }                                                                       \
    }

    LOADCH(0);
    for (int k0 = 0; k0 < Keff; k0 += BK) {
        STORECH();
        __syncthreads();
        if (k0 + BK < Keff) LOADCH(k0 + BK);   // overlaps MMA below

        uint32_t bhf[4][2];
#pragma unroll
        for (int nf = 0; nf < 4; nf++) {
            int nb = (wn << 5) + (nf << 3) + gp;
            bhf[nf][0] = Bh[nb * PK + tg];
            bhf[nf][1] = Bh[nb * PK + tg + 4];
        }
#pragma unroll
        for (int mf = 0; mf < 4; mf++) {
            int mb = (wm << 6) + (mf << 4) + gp;
            int j0 = mb * PK + tg;
            int j1 = (mb + 8) * PK + tg;
            uint32_t ahf[4] = { Ah[j0], Ah[j1], Ah[j0 + 4], Ah[j1 + 4] };
#pragma unroll
            for (int nf = 0; nf < 4; nf++)
                mma16(acc[mf][nf], ahf, bhf[nf]);
        }
        __syncthreads();
    }
#undef LOADCH
#undef STORECH

    // ---- store
#pragma unroll
    for (int mf = 0; mf < 4; mf++) {
#pragma unroll
        for (int nf = 0; nf < 4; nf++) {
            int n = n0 + (wn << 5) + (nf << 3) + 2 * tg;
#pragma unroll
            for (int h = 0; h < 2; h++) {
                int m = m0 + (wm << 6) + (mf << 4) + gp + h * 8;
                float2 v = make_float2(acc[mf][nf][2 * h], acc[mf][nf][2 * h + 1]);
                if (EPI == 1) {
                    v.x = v.x * SCALEV + ((n + 0 > m) ? NEGV : 0.f);
                    v.y = v.y * SCALEV + ((n + 1 > m) ? NEGV : 0.f);
                }
                LL ro = (LL)m * ldc;
                if (n + 1 < N) {
                    *reinterpret_cast<float2*>(C + ro + n) = v;
                } else {
                    if (n < N) C[ro + n] = v.x;
                    if (n + 1 < N) C[ro + n + 1] = v.y;
                }
            }
        }
    }
}

// ---- weight concat: wcat[k][0:1536]=wq_a[k], wcat[k][1536:2112]=wkv_a[k] ----
__global__ void wconcat_k(const float* __restrict__ wq_a,
                          const float* __restrict__ wkv_a,
                          float* __restrict__ wcat)
{
    int idx = blockIdx.x * 256 + threadIdx.x;          // float4 index
    int row = idx / (QKVW / 4);
    int c4  = idx - row * (QKVW / 4);
    if (row >= DIM) return;
    int c = c4 * 4;
    float4 v;
    if (c < QL) v = *reinterpret_cast<const float4*>(wq_a + (LL)row * QL + c);
    else        v = *reinterpret_cast<const float4*>(wkv_a + (LL)row * CAT + (c - QL));
    *reinterpret_cast<float4*>(wcat + (LL)row * QKVW + c) = v;
}

// ---------------- rmsnorm (in place, strided rows) ----------------
__global__ void rmsnorm_k(float* __restrict__ x, const float* __restrict__ w,
                          int len, int stride)
{
    float* row = x + (LL)blockIdx.x * stride;
    const int tid = threadIdx.x;
    float ss = 0.f;
    for (int i = tid; i < len; i += 256) { float v = row[i]; ss += v * v; }
    __shared__ float red[8];
    __shared__ float sc_s;
#pragma unroll
    for (int o = 16; o; o >>= 1) ss += __shfl_xor_sync(0xffffffffu, ss, o);
    if ((tid & 31) == 0) red[tid >> 5] = ss;
    __syncthreads();
    if (tid == 0) {
        float t = 0.f;
#pragma unroll
        for (int i = 0; i < 8; i++) t += red[i];
        sc_s = rsqrtf(t / (float)len + EPSV);
    }
    __syncthreads();
    float sc = sc_s;
    for (int i = tid; i < len; i += 256) row[i] = row[i] * sc * w[i];
}

// ---- kvpost: rmsnorm(c_kv)*w -> kvcat[0:512]; rope(k_pe) -> kvcat[512:576]
//      AND broadcast roped k_pe into KV[b][h][t][256:320] for all 32 heads.
__global__ void kvpost_k(const float* __restrict__ kv, const float* __restrict__ w,
                         const float* __restrict__ fc, float* __restrict__ o,
                         float* __restrict__ KV, int stride)
{
    const int bs = blockIdx.x;
    const float* row = kv + (LL)bs * stride;
    float* out = o + (LL)bs * CAT;
    const int tid = threadIdx.x;
    float2 v = *reinterpret_cast<const float2*>(row + 2 * tid);
    float ss = v.x * v.x + v.y * v.y;
    __shared__ float red[8];
    __shared__ float sc_s;
#pragma unroll
    for (int oo = 16; oo; oo >>= 1) ss += __shfl_xor_sync(0xffffffffu, ss, oo);
    if ((tid & 31) == 0) red[tid >> 5] = ss;
    __syncthreads();
    if (tid == 0) {
        float t = 0.f;
#pragma unroll
        for (int i = 0; i < 8; i++) t += red[i];
        sc_s = rsqrtf(t / (float)KVL + EPSV);
    }
    __syncthreads();
    float sc = sc_s;
    *reinterpret_cast<float2*>(out + 2 * tid) =
        make_float2(v.x * sc * w[2 * tid], v.y * sc * w[2 * tid + 1]);
    if (tid < 32) {
        int t = bs & (SS - 1);
        int b = bs >> 10;
        float e  = row[KVL + 2 * tid];
        float od = row[KVL + 2 * tid + 1];
        float c  = fc[t * ROPE + 2 * tid];
        float sn = fc[t * ROPE + 2 * tid + 1];
        float re = e * c - od * sn;
        float ro = e * sn + od * c;
        out[KVL + 2 * tid]     = re;
        out[KVL + 2 * tid + 1] = ro;
        float2 pr = make_float2(re, ro);
#pragma unroll
        for (int h = 0; h < HH; h++) {
            LL base = (((LL)(b * HH + h)) * SS + t) * KVW + 256 + 2 * tid;
            *reinterpret_cast<float2*>(KV + base) = pr;
        }
    }
}

// ---- rope(q_pe) IN PLACE on q[..., h*192+128 : h*192+192] ----
__global__ void ropeq_k(float* __restrict__ q, const float* __restrict__ fc)
{
    const int bs = blockIdx.x;
    const int s = bs & (SS - 1);
    for (int t = threadIdx.x; t < HH * 32; t += 256) {
        int h = t >> 5, i = t & 31;
        float* p = q + (LL)bs * QD + h * QKH + NOPE + 2 * i;
        float e = p[0], o = p[1];
        float c  = fc[s * ROPE + 2 * i];
        float sn = fc[s * ROPE + 2 * i + 1];
        p[0] = e * c - o * sn;
        p[1] = e * sn + o * c;
    }
}

// ---- softmax stats (single gmem pass, register-cached) ----
__global__ void smstat_k(const float* __restrict__ S, float2* __restrict__ stat)
{
    const LL row = blockIdx.x;               // bh*1024 + m
    const int m = (int)(row & (SS - 1));
    const float* r = S + row * SS;
    const int tid = threadIdx.x;             // 128 threads
    float v[8];
    int cnt = 0;
    float mx = -3.4e38f;
    for (int i = tid; i <= m; i += 128) {
        float x = r[i];
        v[cnt++] = x;
        mx = fmaxf(mx, x);
    }
    __shared__ float red[4];
    __shared__ float bval;
#pragma unroll
    for (int o = 16; o; o >>= 1) mx = fmaxf(mx, __shfl_xor_sync(0xffffffffu, mx, o));
    if ((tid & 31) == 0) red[tid >> 5] = mx;
    __syncthreads();
    if (tid == 0) {
        float t = fmaxf(fmaxf(red[0], red[1]), fmaxf(red[2], red[3]));
        bval = t;
    }
    __syncthreads();
    mx = bval;
    float sum = 0.f;
    for (int j = 0; j < cnt; j++) sum += __expf(v[j] - mx);
#pragma unroll
    for (int o = 16; o; o >>= 1) sum += __shfl_xor_sync(0xffffffffu, sum, o);
    if ((tid & 31) == 0) red[tid >> 5] = sum;
    __syncthreads();
    if (tid == 0) {
        float t = red[0] + red[1] + red[2] + red[3];
        stat[row] = make_float2(mx, 1.f / t);
    }
}

// ---------------- host ----------------
extern "C" void kernel_launch(void* const* d_in, const int* in_sizes, int n_in,
                              void* d_out, int out_size)
{
    (void)in_sizes; (void)n_in; (void)out_size;
    const float* x      = (const float*)d_in[0];
    const float* fc     = (const float*)d_in[1];
    /* mask d_in[2] handled analytically (start_pos == 0, causal) */
    const float* wq_a   = (const float*)d_in[3];
    const float* qnw    = (const float*)d_in[4];
    const float* wq_b   = (const float*)d_in[5];
    const float* wkv_a  = (const float*)d_in[6];
    const float* kvnw   = (const float*)d_in[7];
    const float* wkv_b  = (const float*)d_in[8];
    const float* wo     = (const float*)d_in[9];
    float* out = (float*)d_out;

    float *wcat, *qkv, *kvcat, *q, *KV, *scores, *proj;
    float2* sstat;
    cudaGetSymbolAddress((void**)&wcat,   g_wcat);
    cudaGetSymbolAddress((void**)&qkv,    g_qkv);
    cudaGetSymbolAddress((void**)&kvcat,  g_kvcat);
    cudaGetSymbolAddress((void**)&q,      g_q);
    cudaGetSymbolAddress((void**)&KV,     g_KV);
    cudaGetSymbolAddress((void**)&scores, g_scores);
    cudaGetSymbolAddress((void**)&sstat,  g_sstat);
    cudaGetSymbolAddress((void**)&proj,   g_proj);

    // one-time stream/event setup (outside graph capture; capture encodes fork)
    static cudaStream_t s2 = nullptr;
    static cudaEvent_t evA = nullptr, evB = nullptr;
    if (s2 == nullptr) {
        cudaStreamCreateWithFlags(&s2, cudaStreamNonBlocking);
        cudaEventCreateWithFlags(&evA, cudaEventDisableTiming);
        cudaEventCreateWithFlags(&evB, cudaEventDisableTiming);
    }

    // 0. wcat = [wq_a ‖ wkv_a]
    wconcat_k<<<(DIM * (QKVW / 4) + 255) / 256, 256>>>(wq_a, wkv_a, wcat);
    // 1+2 fused. qkv = x @ wcat          [2048,2112]
    gemm_k<false, 0, false, 0, 0><<<dim3(17, 16, 1), 256>>>(
        x, wcat, qkv, BS, QKVW, DIM, DIM, QKVW, QKVW, 0, 0, 0, 0, 0, 0, 1, nullptr);
    // 3. rmsnorm(qlora) in place (rows inside qkv, stride 2112)
    rmsnorm_k<<<BS, 256>>>(qkv, qnw, QL, QKVW);
    // 4. kvpost -> kvcat; k_pe broadcast into KV[...,256:320]
    kvpost_k<<<BS, 256>>>(qkv + QL, kvnw, fc, kvcat, KV, QKVW);

    // ---- fork: kv branch on s2, q branch on default stream
    cudaEventRecord(evA, 0);
    cudaStreamWaitEvent(s2, evA, 0);
    // 5 (s2). KV[b][h][t][0:256] = kv_n @ wkv_b[h]^T  (K_head + V)
    gemm_k<true, 0, false, 0, 0><<<dim3(2, 8, 64), 256, 0, s2>>>(
        kvcat, wkv_b, KV, SS, NOPE + VD, KVL,
        CAT, KVL, KVW,
        (LL)SS * CAT, 0,
        0, (LL)(NOPE + VD) * KVL,
        (LL)HH * SS * KVW, (LL)SS * KVW, HH, nullptr);
    cudaEventRecord(evB, s2);
    // 6 (default). q = qlora @ wq_b      [2048,6144]
    gemm_k<false, 0, false, 0, 0><<<dim3(48, 16, 1), 256>>>(
        qkv, wq_b, q, BS, QD, QL, QKVW, QD, QD, 0, 0, 0, 0, 0, 0, 1, nullptr);
    // 7 (default). rope(q_pe) in place on q
    ropeq_k<<<BS, 256>>>(q, fc);
    // ---- join
    cudaStreamWaitEvent(0, evB, 0);

    // 8. scores = q_head @ [K_head|k_pe]^T (*SCALE + causal; KREMAP)
    gemm_k<true, 1, false, 0, 1><<<dim3(8, 8, 64), 256>>>(
        q, KV, scores, SS, SS, QKH,
        QD, KVW, SS,
        (LL)SS * QD, QKH,
        (LL)HH * SS * KVW, (LL)SS * KVW,
        (LL)HH * SS * SS, (LL)SS * SS, HH, nullptr);
    // 9. per-row softmax stats over causal prefix (single pass)
    smstat_k<<<64 * SS, 128>>>(scores, sstat);
    // 10. PV: proj = softmax(scores) @ V (fused, causal K; non-TB)
    gemm_k<false, 0, true, 1, 0><<<dim3(1, 8, 64), 256>>>(
        scores, KV + 128, proj, SS, VD, SS,
        SS, KVW, DIM,
        (LL)HH * SS * SS, (LL)SS * SS,
        (LL)HH * SS * KVW, (LL)SS * KVW,
        (LL)SS * DIM, VD, HH, sstat);
    // 11. out = proj @ wo                [2048,4096]
    gemm_k<false, 0, false, 0, 0><<<dim3(32, 16, 1), 256>>>(
        proj, wo, out, BS, DIM, DIM, DIM, DIM, DIM, 0, 0, 0, 0, 0, 0, 1, nullptr);
}